// round 15
// baseline (speedup 1.0000x reference)
#include <cuda_runtime.h>
#include <cstdint>

#define SDIM  16
#define NNODE 256
#define VDIM  64
#define EDIM  64
#define HDIM  16
#define KEDGE 255   // N-1
#define NSN   (SDIM * NNODE)
#define NPROD 256   // producer blocks; 16 per s-slice

typedef unsigned long long ull;

// per-node projections, pr stored TRANSPOSED: g_prT[s][e][n]
__device__ float g_prT[SDIM * HDIM * NNODE];
__device__ float g_psb[SDIM * NNODE * HDIM];   // psb[sn][e] = v0@we1[64:128]+be1
__device__ unsigned int g_done[SDIM];          // per-s producer counters (monotone)
__device__ float g_evpart[NSN * 2 * EDIM];     // per-half partial ev sums
__device__ unsigned int g_tile_done[NSN];      // atomicInc mod-2: cycles 0->1->0
                                               // (replay-safe; partials rewritten
                                               //  with identical values each run)

__device__ __forceinline__ float fast_tanh(float x) {
    // tanh(x) = 1 - 2/(e^{2x}+1); robust at +/-inf, MUFU-based, ~1e-6 rel err
    float y = __expf(2.0f * x);
    return 1.0f - __fdividef(2.0f, y + 1.0f);
}
__device__ __forceinline__ ull pack2(float a, float b) {
    ull u; asm("mov.b64 %0, {%1, %2};" : "=l"(u) : "f"(a), "f"(b)); return u;
}

// ---------------------------------------------------------------------------
// Half-tile fused kernel: 8192 blocks; block bid handles tile sn=bid>>1,
// half h2=bid&1 (edges/rows [128*h2, 128*h2+128) of the tile).
//  - halves the partial-tail-wave waste (9.22 waves of full tiles -> half quanta)
//  - body per half = R13: natural-pair tanh table (8KB), lane owns channels
//    2l,2l+1 (32-reg h-pair weights), f32x2 FFMA, 4-deep e0 register pipeline,
//    prefetch chain (prologue covers refills; refill prefetch covers the NEXT
//    half's prologue), streaming .cs stores.
//  - dv: each half writes its 64-float partial ev; second finisher (atomicInc
//    mod-2 == 1) sums part0+part1 (fixed order) and runs the node MLP.
//  - proj producers: blocks 0..255 (earliest scheduled) fill g_prT/g_psb and
//    bump g_done[s]; consumers poll their slice's flag before the tanh table.
// ---------------------------------------------------------------------------
__global__ void __launch_bounds__(256, 3) mega_kernel(
    const float* __restrict__ v0,
    const float* __restrict__ e0,
    const float* __restrict__ wv1, const float* __restrict__ bv1,
    const float* __restrict__ wv2, const float* __restrict__ bv2,
    const float* __restrict__ we1, const float* __restrict__ be1,
    const float* __restrict__ we2, const float* __restrict__ be2,
    float* __restrict__ dv_out, float* __restrict__ de_out)
{
    __shared__ union SM {
        float vs[16][VDIM];                                          // proj stage
        ulonglong2 tt2[4][128];                                      // 8 KB table
        struct { float4 part[16][17]; float evs[EDIM]; float hv[HDIM]; } node;
    } sm;
    __shared__ float psb_s[HDIM];
    __shared__ unsigned int finflag;

    const int bid = blockIdx.x;
    const int sn  = bid >> 1;             // tile (s*256 + n)
    const int h2  = bid & 1;              // half index
    const int kb  = h2 << 7;              // edge/row base: 0 or 128
    const int s   = sn >> 8;
    const int i   = sn & 255;
    const int tid = threadIdx.x;
    const int w   = tid >> 5;             // warp 0..7
    const int l   = tid & 31;             // lane
    const int c4  = l & 15;               // float4 slot in 64-wide channel dim
    const int r0  = w * 2 + (l >> 4);     // 0..15 row offset within 16-row groups
    const int c0  = l << 1;               // owned channels c0, c0+1

    const bool pf = ((c4 & 7) == 0) && (sn != NSN - 1);

    const float4* e0p = reinterpret_cast<const float4*>(e0)
                      + (size_t)sn * (KEDGE * EDIM / 4);

    // prologue: rows kb..kb+63 (all valid) + prefetch rows kb+64..kb+127
    float4 buf[4];
    #pragma unroll
    for (int u = 0; u < 4; u++) {
        const float4* p = &e0p[(kb + u * 16 + r0) * 16 + c4];
        buf[u] = __ldcs(p);
        if (pf) asm volatile("prefetch.global.L2 [%0];" :: "l"(p + 1024));
    }

    // ---- producer phase: block b (<256) covers s=b>>4, node group b&15 ----
    if (bid < NPROD) {
        const int ps = bid >> 4;
        const int pg = bid & 15;
        const int nl = tid >> 4;
        const int h  = tid & 15;
        const int pn = (ps << 8) + (pg << 4) + nl;
        {
            const float4* src = reinterpret_cast<const float4*>(v0)
                              + (size_t)((ps << 8) + (pg << 4)) * 16;
            reinterpret_cast<float4*>(&sm.vs[0][0])[tid] = src[tid];
        }
        __syncthreads();

        float pr  = 0.f;
        float psb = be1[h];
        #pragma unroll
        for (int e = 0; e < VDIM; e++) {
            float v = sm.vs[nl][e];
            pr  = fmaf(v, we1[e * HDIM + h], pr);
            psb = fmaf(v, we1[(VDIM + e) * HDIM + h], psb);
        }
        g_prT[(ps * HDIM + h) * NNODE + (pn & 255)] = pr;   // transposed
        g_psb[pn * HDIM + h] = psb;

        __threadfence();
        __syncthreads();
        if (tid == 0) atomicAdd(&g_done[ps], 1u);
    }

    // lane weights: h-pair packed for channels c0, c0+1 -> 16 ull (32 regs)
    ull wa[8], wb[8];
    #pragma unroll
    for (int m = 0; m < 8; m++) {
        wa[m] = pack2(we2[(2 * m) * VDIM + c0    ], we2[(2 * m + 1) * VDIM + c0    ]);
        wb[m] = pack2(we2[(2 * m) * VDIM + c0 + 1], we2[(2 * m + 1) * VDIM + c0 + 1]);
    }
    const ull Ba = pack2(be2[c0    ], 0.0f);
    const ull Bb = pack2(be2[c0 + 1], 0.0f);

    // ---- wait for THIS s-slice's 16 producers ----
    if (tid == 0) {
        unsigned int d;
        do {
            asm volatile("ld.acquire.gpu.global.u32 %0, [%1];"
                         : "=r"(d) : "l"(&g_done[s]));
            if (d >= 16u) break;
            __nanosleep(64);
        } while (true);
    }
    __syncthreads();

    if (tid < 4)
        reinterpret_cast<float4*>(psb_s)[tid] =
            reinterpret_cast<const float4*>(g_psb + sn * HDIM)[tid];
    __syncthreads();

    // --- tanh table for THIS half's 128 edges (local index = tid) ---
    if (tid < 128) {
        const int k = kb + tid;
        if (k < KEDGE) {
            const int j = k + (k >= i);   // skip diagonal
            const float* prb = g_prT + s * HDIM * NNODE + j;
            #pragma unroll
            for (int m = 0; m < 4; m++) {
                float t0 = fast_tanh(__ldg(prb + (4*m  ) * NNODE) + psb_s[4*m  ]);
                float t1 = fast_tanh(__ldg(prb + (4*m+1) * NNODE) + psb_s[4*m+1]);
                float t2 = fast_tanh(__ldg(prb + (4*m+2) * NNODE) + psb_s[4*m+2]);
                float t3 = fast_tanh(__ldg(prb + (4*m+3) * NNODE) + psb_s[4*m+3]);
                sm.tt2[m][tid] = make_ulonglong2(pack2(t0, t1), pack2(t2, t3));
            }
        }
    }
    __syncthreads();

    ull accA = 0, accB = 0;
    float* outp = de_out + (size_t)sn * KEDGE * VDIM + c0;

#define EDGE_ITER(KL) do {                                                     \
        const int kl_ = (KL);                                                  \
        const int k_  = kb + kl_;                                              \
        if (k_ < KEDGE) {                                                      \
            ull Aa0 = Ba, Aa1 = 0, Ab0 = Bb, Ab1 = 0;                          \
            _Pragma("unroll")                                                  \
            for (int m = 0; m < 4; m++) {                                      \
                ulonglong2 tp = sm.tt2[m][kl_];         /* broadcast LDS.128 */\
                asm("fma.rn.f32x2 %0, %1, %2, %0;" : "+l"(Aa0) : "l"(wa[2*m  ]), "l"(tp.x)); \
                asm("fma.rn.f32x2 %0, %1, %2, %0;" : "+l"(Ab0) : "l"(wb[2*m  ]), "l"(tp.x)); \
                asm("fma.rn.f32x2 %0, %1, %2, %0;" : "+l"(Aa1) : "l"(wa[2*m+1]), "l"(tp.y)); \
                asm("fma.rn.f32x2 %0, %1, %2, %0;" : "+l"(Ab1) : "l"(wb[2*m+1]), "l"(tp.y)); \
            }                                                                  \
            asm("add.rn.f32x2 %0, %0, %1;" : "+l"(Aa0) : "l"(Aa1));            \
            asm("add.rn.f32x2 %0, %0, %1;" : "+l"(Ab0) : "l"(Ab1));            \
            float a_lo, a_hi, b_lo, b_hi;                                      \
            asm("mov.b64 {%0, %1}, %2;" : "=f"(a_lo), "=f"(a_hi) : "l"(Aa0));  \
            asm("mov.b64 {%0, %1}, %2;" : "=f"(b_lo), "=f"(b_hi) : "l"(Ab0));  \
            float2 o_ = make_float2(a_lo + a_hi, b_lo + b_hi);                 \
            __stcs(reinterpret_cast<float2*>(outp + (size_t)k_ * VDIM), o_);   \
        }                                                                      \
    } while (0)

    // --- main loop: 8 groups; per group 2 edge iters + consume; g<4 also
    //     refill (+prefetch next half's prologue rows) ---
    #pragma unroll 1
    for (int gb = 0; gb < 8; gb += 4) {
        #pragma unroll
        for (int u = 0; u < 4; u++) {
            const int g = gb + u;
            EDGE_ITER(16 * g     + w);
            EDGE_ITER(16 * g + 8 + w);
            {
                float4 v = buf[u];
                const int r = kb + g * 16 + r0;
                if (r < KEDGE) {
                    ull va = pack2(v.x, v.y), vb = pack2(v.z, v.w);
                    asm("add.rn.f32x2 %0, %0, %1;" : "+l"(accA) : "l"(va));
                    asm("add.rn.f32x2 %0, %0, %1;" : "+l"(accB) : "l"(vb));
                }
                if (g < 4) {
                    const int rn = r + 64;
                    const float4* p = &e0p[rn * 16 + c4];
                    if (rn < KEDGE) buf[u] = __ldcs(p);
                    // prefetch rows rn+64 (next half's prologue / next tile)
                    if (pf) asm volatile("prefetch.global.L2 [%0];" :: "l"(p + 1024));
                }
            }
        }
    }
#undef EDGE_ITER

    // --- epilogue: reduce this half's e0 partials, publish, finisher does MLP ---
    float4 acc;
    asm("mov.b64 {%0, %1}, %2;" : "=f"(acc.x), "=f"(acc.y) : "l"(accA));
    asm("mov.b64 {%0, %1}, %2;" : "=f"(acc.z), "=f"(acc.w) : "l"(accB));

    __syncthreads();                      // tt2 reads done; part may reuse smem
    sm.node.part[r0][c4] = acc;
    __syncthreads();

    if (tid < 16) {
        float4 p4 = sm.node.part[0][tid];
        #pragma unroll
        for (int g = 1; g < 16; g++) {
            float4 p = sm.node.part[g][tid];
            p4.x += p.x; p4.y += p.y; p4.z += p.z; p4.w += p.w;
        }
        reinterpret_cast<float4*>(g_evpart + (size_t)bid * EDIM)[tid] = p4;
    }
    __threadfence();                      // publish partial before signalling
    __syncthreads();
    if (tid == 0) finflag = atomicInc(&g_tile_done[sn], 1u);  // 0->1->0 cycle
    __syncthreads();

    if (finflag == 1u) {                  // second finisher computes dv
        __threadfence();                  // see the other half's partial
        if (tid < 16) {
            float4 a0 = reinterpret_cast<const float4*>(g_evpart + (size_t)(sn*2  ) * EDIM)[tid];
            float4 a1 = reinterpret_cast<const float4*>(g_evpart + (size_t)(sn*2+1) * EDIM)[tid];
            a0.x += a1.x; a0.y += a1.y; a0.z += a1.z; a0.w += a1.w;
            reinterpret_cast<float4*>(sm.node.evs)[tid] = a0;
        }
        __syncthreads();

        if (tid < 16) {
            float v = bv1[tid];
            #pragma unroll
            for (int e = 0; e < EDIM; e++) v = fmaf(sm.node.evs[e], wv1[e * HDIM + tid], v);
            sm.node.hv[tid] = fast_tanh(v);
        }
        __syncthreads();

        if (tid < VDIM) {
            float v = bv2[tid];
            #pragma unroll
            for (int j = 0; j < HDIM; j++) v = fmaf(sm.node.hv[j], wv2[j * VDIM + tid], v);
            dv_out[(size_t)sn * VDIM + tid] = v;
        }
    }
}

// ---------------------------------------------------------------------------
// inputs (metadata order): t, v0, e0, wv1, bv1, wv2, bv2, we1, be1, we2, be2,
//                          recv_idx, send_idx (idx arrays unused: analytic)
// output: dv (S,N,V) followed by de (S,N,N-1,E)
// ---------------------------------------------------------------------------
extern "C" void kernel_launch(void* const* d_in, const int* in_sizes, int n_in,
                              void* d_out, int out_size)
{
    const float* v0  = (const float*)d_in[1];
    const float* e0  = (const float*)d_in[2];
    const float* wv1 = (const float*)d_in[3];
    const float* bv1 = (const float*)d_in[4];
    const float* wv2 = (const float*)d_in[5];
    const float* bv2 = (const float*)d_in[6];
    const float* we1 = (const float*)d_in[7];
    const float* be1 = (const float*)d_in[8];
    const float* we2 = (const float*)d_in[9];
    const float* be2 = (const float*)d_in[10];

    float* dv_out = (float*)d_out;
    float* de_out = dv_out + (size_t)SDIM * NNODE * VDIM;

    mega_kernel<<<NSN * 2, 256>>>(v0, e0, wv1, bv1, wv2, bv2, we1, be1, we2, be2,
                                  dv_out, de_out);
}

// round 16
// speedup vs baseline: 1.4547x; 1.4547x over previous
#include <cuda_runtime.h>
#include <cstdint>

#define SDIM  16
#define NNODE 256
#define VDIM  64
#define EDIM  64
#define HDIM  16
#define KEDGE 255   // N-1
#define NSN   (SDIM * NNODE)
#define NPROD 256   // producer blocks; 16 per s-slice

typedef unsigned long long ull;

// per-node projections, pr stored TRANSPOSED: g_prT[s][e][n]
__device__ float g_prT[SDIM * HDIM * NNODE];
__device__ float g_psb[SDIM * NNODE * HDIM];   // psb[sn][e] = v0@we1[64:128] + be1
__device__ unsigned int g_done[SDIM];          // per-s producer counters
                                               // (monotone across graph replays;
                                               //  producers rewrite identical values)

__device__ __forceinline__ float fast_tanh(float x) {
    // tanh(x) = 1 - 2/(e^{2x}+1); robust at +/-inf, MUFU-based, ~1e-6 rel err
    float y = __expf(2.0f * x);
    return 1.0f - __fdividef(2.0f, y + 1.0f);
}
__device__ __forceinline__ ull pack2(float a, float b) {
    ull u; asm("mov.b64 %0, {%1, %2};" : "=l"(u) : "f"(a), "f"(b)); return u;
}

// ---------------------------------------------------------------------------
// Fused kernel (R13 + deeper prefetch): one block per (s,n) tile.
// Blocks 0..255: producer b covers (s = b>>4, nodes 16*(b&15)..+15) and bumps
// g_done[s]. Consumer sn polls only g_done[sn>>8] >= 16.
// Tile body: natural-pair tanh table (16KB smem), lane owns channels 2l,2l+1
// (32-reg h-pair-packed weights), one warp per edge, f32x2 FFMA; e0 reads in
// a 4-deep register pipeline. Prefetch runs TWO buffer-depths ahead (+128
// rows): prologue prefetches rows 64..191, each refill prefetches its LDG
// row +128 (consumed ~8 groups later -> full ~600cyc DRAM latency coverage).
// de stores streaming STG.64 .cs.
// ---------------------------------------------------------------------------
__global__ void __launch_bounds__(256, 3) mega_kernel(
    const float* __restrict__ v0,
    const float* __restrict__ e0,
    const float* __restrict__ wv1, const float* __restrict__ bv1,
    const float* __restrict__ wv2, const float* __restrict__ bv2,
    const float* __restrict__ we1, const float* __restrict__ be1,
    const float* __restrict__ we2, const float* __restrict__ be2,
    float* __restrict__ dv_out, float* __restrict__ de_out)
{
    __shared__ union SM {
        float vs[16][VDIM];                                          // proj stage
        ulonglong2 tt2[4][256];                                      // 16 KB
        struct { float4 part[16][17]; float evs[EDIM]; float hv[HDIM]; } node;
    } sm;
    __shared__ float psb_s[HDIM];

    const int sn  = blockIdx.x;           // s*256 + n  (n is also edge-row i)
    const int s   = sn >> 8;
    const int i   = sn & 255;
    const int tid = threadIdx.x;
    const int w   = tid >> 5;             // warp 0..7 == edge slot
    const int l   = tid & 31;             // lane
    const int c4  = l & 15;               // float4 slot in 64-wide channel dim
    const int r0  = w * 2 + (l >> 4);     // 0..15: row offset within 16-row groups
    const int c0  = l << 1;               // owned channels c0, c0+1

    const bool pf = ((c4 & 7) == 0) && (sn != NSN - 1);

    const float4* e0p = reinterpret_cast<const float4*>(e0)
                      + (size_t)sn * (KEDGE * EDIM / 4);

    // prologue: buf rows 0..63 + prefetch rows 64..191 (two buffer depths)
    float4 buf[4];
    #pragma unroll
    for (int u = 0; u < 4; u++) {
        const float4* p = &e0p[(u * 16 + r0) * 16 + c4];
        buf[u] = __ldcs(p);
        if (pf) {
            asm volatile("prefetch.global.L2 [%0];" :: "l"(p + 1024));
            asm volatile("prefetch.global.L2 [%0];" :: "l"(p + 2048));
        }
    }

    // ---- producer phase: block b covers s=b>>4, node group b&15 ----
    if (sn < NPROD) {
        const int ps = sn >> 4;           // produced s-slice
        const int pg = sn & 15;           // node group within slice
        const int nl = tid >> 4;          // node 0..15 within group
        const int h  = tid & 15;          // h-dim
        const int pn = (ps << 8) + (pg << 4) + nl;   // global (s,n)
        {
            const float4* src = reinterpret_cast<const float4*>(v0)
                              + (size_t)((ps << 8) + (pg << 4)) * 16;
            reinterpret_cast<float4*>(&sm.vs[0][0])[tid] = src[tid];
        }
        __syncthreads();

        float pr  = 0.f;
        float psb = be1[h];
        #pragma unroll
        for (int e = 0; e < VDIM; e++) {
            float v = sm.vs[nl][e];
            pr  = fmaf(v, we1[e * HDIM + h], pr);
            psb = fmaf(v, we1[(VDIM + e) * HDIM + h], psb);
        }
        g_prT[(ps * HDIM + h) * NNODE + (pn & 255)] = pr;   // transposed
        g_psb[pn * HDIM + h] = psb;

        __threadfence();                  // release prT/psb before signalling
        __syncthreads();                  // all 256 stores of this block done
        if (tid == 0) atomicAdd(&g_done[ps], 1u);
    }

    // lane weights: h-pair packed for channels c0, c0+1 -> 16 ull (32 regs)
    ull wa[8], wb[8];
    #pragma unroll
    for (int m = 0; m < 8; m++) {
        wa[m] = pack2(we2[(2 * m) * VDIM + c0    ], we2[(2 * m + 1) * VDIM + c0    ]);
        wb[m] = pack2(we2[(2 * m) * VDIM + c0 + 1], we2[(2 * m + 1) * VDIM + c0 + 1]);
    }
    const ull Ba = pack2(be2[c0    ], 0.0f);   // bias folded into accum init
    const ull Bb = pack2(be2[c0 + 1], 0.0f);

    // ---- wait for THIS s-slice's 16 producers (acquire), then load psb ----
    if (tid == 0) {
        unsigned int d;
        do {
            asm volatile("ld.acquire.gpu.global.u32 %0, [%1];"
                         : "=r"(d) : "l"(&g_done[s]));
            if (d >= 16u) break;
            __nanosleep(64);
        } while (true);
    }
    __syncthreads();                      // slice readiness visible to block

    if (tid < 4)
        reinterpret_cast<float4*>(psb_s)[tid] =
            reinterpret_cast<const float4*>(g_psb + sn * HDIM)[tid];
    __syncthreads();                      // psb_s visible

    // --- tanh table: thread k computes t[k][0..15] in natural order ---
    if (tid < KEDGE) {
        const int j = tid + (tid >= i);   // skip diagonal
        const float* prb = g_prT + s * HDIM * NNODE + j;
        #pragma unroll
        for (int m = 0; m < 4; m++) {
            float t0 = fast_tanh(__ldg(prb + (4 * m    ) * NNODE) + psb_s[4 * m    ]);
            float t1 = fast_tanh(__ldg(prb + (4 * m + 1) * NNODE) + psb_s[4 * m + 1]);
            float t2 = fast_tanh(__ldg(prb + (4 * m + 2) * NNODE) + psb_s[4 * m + 2]);
            float t3 = fast_tanh(__ldg(prb + (4 * m + 3) * NNODE) + psb_s[4 * m + 3]);
            sm.tt2[m][tid] = make_ulonglong2(pack2(t0, t1), pack2(t2, t3));
        }
    }
    __syncthreads();                      // table ready

    ull accA = 0, accB = 0;               // packed e0 partial sums
    float* outp = de_out + (size_t)sn * KEDGE * VDIM + c0;

#define EDGE_ITER(K) do {                                                      \
        const int k_ = (K);                                                    \
        if (k_ < KEDGE) {                                                      \
            ull Aa0 = Ba, Aa1 = 0, Ab0 = Bb, Ab1 = 0;                          \
            _Pragma("unroll")                                                  \
            for (int m = 0; m < 4; m++) {                                      \
                ulonglong2 tp = sm.tt2[m][k_];          /* broadcast LDS.128 */\
                asm("fma.rn.f32x2 %0, %1, %2, %0;" : "+l"(Aa0) : "l"(wa[2*m  ]), "l"(tp.x)); \
                asm("fma.rn.f32x2 %0, %1, %2, %0;" : "+l"(Ab0) : "l"(wb[2*m  ]), "l"(tp.x)); \
                asm("fma.rn.f32x2 %0, %1, %2, %0;" : "+l"(Aa1) : "l"(wa[2*m+1]), "l"(tp.y)); \
                asm("fma.rn.f32x2 %0, %1, %2, %0;" : "+l"(Ab1) : "l"(wb[2*m+1]), "l"(tp.y)); \
            }                                                                  \
            asm("add.rn.f32x2 %0, %0, %1;" : "+l"(Aa0) : "l"(Aa1));            \
            asm("add.rn.f32x2 %0, %0, %1;" : "+l"(Ab0) : "l"(Ab1));            \
            float a_lo, a_hi, b_lo, b_hi;                                      \
            asm("mov.b64 {%0, %1}, %2;" : "=f"(a_lo), "=f"(a_hi) : "l"(Aa0));  \
            asm("mov.b64 {%0, %1}, %2;" : "=f"(b_lo), "=f"(b_hi) : "l"(Ab0));  \
            float2 o_ = make_float2(a_lo + a_hi, b_lo + b_hi);                 \
            __stcs(reinterpret_cast<float2*>(outp + (size_t)k_ * VDIM), o_);   \
        }                                                                      \
    } while (0)

    // --- pipelined main loop: 16 groups; per group 2 edge iters + 1 LDG
    //     + 1 prefetch (TWO buffer-depths ahead of the LDG) ---
    #pragma unroll 1
    for (int gb = 0; gb < 16; gb += 4) {
        #pragma unroll
        for (int u = 0; u < 4; u++) {
            const int g = gb + u;
            EDGE_ITER(16 * g     + w);
            EDGE_ITER(16 * g + 8 + w);
            // consume buf[u] (row group g), then refill with group g+4
            {
                float4 v = buf[u];
                const int r = g * 16 + r0;
                if (r < KEDGE) {
                    ull va = pack2(v.x, v.y), vb = pack2(v.z, v.w);
                    asm("add.rn.f32x2 %0, %0, %1;" : "+l"(accA) : "l"(va));
                    asm("add.rn.f32x2 %0, %0, %1;" : "+l"(accB) : "l"(vb));
                }
                const int rn = r + 64;
                const float4* p = &e0p[rn * 16 + c4];
                if (rn < KEDGE) buf[u] = __ldcs(p);
                // prefetch row rn+128 (consumed ~8 groups later; may spill
                // into the next tile: still useful)
                if (pf) asm volatile("prefetch.global.L2 [%0];" :: "l"(p + 2048));
            }
        }
    }
#undef EDGE_ITER

    // --- node epilogue: reduce partials (reuse smem), tiny MLPs ---
    float4 acc;
    asm("mov.b64 {%0, %1}, %2;" : "=f"(acc.x), "=f"(acc.y) : "l"(accA));
    asm("mov.b64 {%0, %1}, %2;" : "=f"(acc.z), "=f"(acc.w) : "l"(accB));

    __syncthreads();                      // everyone done reading tt2
    sm.node.part[r0][c4] = acc;           // 16 owners x 16 c4 slots
    __syncthreads();

    if (tid < 16) {
        float4 p4 = sm.node.part[0][tid];
        #pragma unroll
        for (int g = 1; g < 16; g++) {
            float4 p = sm.node.part[g][tid];
            p4.x += p.x; p4.y += p.y; p4.z += p.z; p4.w += p.w;
        }
        reinterpret_cast<float4*>(sm.node.evs)[tid] = p4;
    }
    __syncthreads();

    if (tid < 16) {
        float v = bv1[tid];
        #pragma unroll
        for (int e = 0; e < EDIM; e++) v = fmaf(sm.node.evs[e], wv1[e * HDIM + tid], v);
        sm.node.hv[tid] = fast_tanh(v);
    }
    __syncthreads();

    if (tid < VDIM) {
        float v = bv2[tid];
        #pragma unroll
        for (int j = 0; j < HDIM; j++) v = fmaf(sm.node.hv[j], wv2[j * VDIM + tid], v);
        dv_out[(size_t)sn * VDIM + tid] = v;
    }
}

// ---------------------------------------------------------------------------
// inputs (metadata order): t, v0, e0, wv1, bv1, wv2, bv2, we1, be1, we2, be2,
//                          recv_idx, send_idx (idx arrays unused: analytic)
// output: dv (S,N,V) followed by de (S,N,N-1,E)
// ---------------------------------------------------------------------------
extern "C" void kernel_launch(void* const* d_in, const int* in_sizes, int n_in,
                              void* d_out, int out_size)
{
    const float* v0  = (const float*)d_in[1];
    const float* e0  = (const float*)d_in[2];
    const float* wv1 = (const float*)d_in[3];
    const float* bv1 = (const float*)d_in[4];
    const float* wv2 = (const float*)d_in[5];
    const float* bv2 = (const float*)d_in[6];
    const float* we1 = (const float*)d_in[7];
    const float* be1 = (const float*)d_in[8];
    const float* we2 = (const float*)d_in[9];
    const float* be2 = (const float*)d_in[10];

    float* dv_out = (float*)d_out;
    float* de_out = dv_out + (size_t)SDIM * NNODE * VDIM;

    mega_kernel<<<NSN, 256>>>(v0, e0, wv1, bv1, wv2, bv2, we1, be1, we2, be2,
                              dv_out, de_out);
}

// round 17
// speedup vs baseline: 1.4798x; 1.0173x over previous
#include <cuda_runtime.h>
#include <cstdint>

#define SDIM  16
#define NNODE 256
#define VDIM  64
#define EDIM  64
#define HDIM  16
#define KEDGE 255   // N-1
#define NSN   (SDIM * NNODE)

typedef unsigned long long ull;

// per-node projections, pr stored TRANSPOSED: g_prT[s][e][n]
__device__ float g_prT[SDIM * HDIM * NNODE];
__device__ float g_psb[SDIM * NNODE * HDIM];   // psb[sn][e] = v0@we1[64:128] + be1

__device__ __forceinline__ float fast_tanh(float x) {
    // tanh(x) = 1 - 2/(e^{2x}+1); robust at +/-inf, MUFU-based, ~1e-6 rel err
    float y = __expf(2.0f * x);
    return 1.0f - __fdividef(2.0f, y + 1.0f);
}
__device__ __forceinline__ ull pack2(float a, float b) {
    ull u; asm("mov.b64 %0, {%1, %2};" : "=l"(u) : "f"(a), "f"(b)); return u;
}

// ---------------------------------------------------------------------------
// Kernel A: per-node projections. 256 blocks x 256 threads, 16 nodes/block.
// Completion (grid end) releases g_prT/g_psb to the PDL-dependent mega kernel.
// ---------------------------------------------------------------------------
__global__ void __launch_bounds__(256) proj_kernel(
    const float* __restrict__ v0,
    const float* __restrict__ we1, const float* __restrict__ be1)
{
    const int tid = threadIdx.x;
    const int nl  = tid >> 4;             // node 0..15 within block
    const int h   = tid & 15;             // output h-dim
    const int sn  = blockIdx.x * 16 + nl;

    __shared__ float vs[16][VDIM];

    {
        const float4* src = reinterpret_cast<const float4*>(v0)
                          + (size_t)blockIdx.x * 16 * 16;
        reinterpret_cast<float4*>(&vs[0][0])[tid] = src[tid];
    }
    __syncthreads();

    float pr  = 0.f;
    float psb = be1[h];
    #pragma unroll
    for (int e = 0; e < VDIM; e++) {
        float v = vs[nl][e];
        pr  = fmaf(v, we1[e * HDIM + h], pr);
        psb = fmaf(v, we1[(VDIM + e) * HDIM + h], psb);
    }
    const int s_idx = sn >> 8;
    const int n_idx = sn & 255;
    g_prT[(s_idx * HDIM + h) * NNODE + n_idx] = pr;   // transposed
    g_psb[sn * HDIM + h] = psb;
}

// ---------------------------------------------------------------------------
// Mega kernel (R9 body + PDL): one block per (s,n), 3 CTAs/SM.
//  Launched with programmatic stream serialization: blocks start while
//  proj_kernel drains; they issue e0 prologue LDGs + prefetches and pack
//  weights, THEN cudaGridDependencySynchronize() gates the first prT read.
//  Body: natural-pair tanh table (16KB), lane owns channels 2l,2l+1
//  (32-reg h-pair weights), one warp per edge, f32x2 FFMA; 4-deep e0
//  register pipeline + prefetch.global.L2 one buffer-depth (+64 rows) ahead;
//  streaming .cs stores.
// ---------------------------------------------------------------------------
__global__ void __launch_bounds__(256, 3) mega_kernel(
    const float* __restrict__ e0,
    const float* __restrict__ wv1, const float* __restrict__ bv1,
    const float* __restrict__ wv2, const float* __restrict__ bv2,
    const float* __restrict__ we2, const float* __restrict__ be2,
    float* __restrict__ dv_out, float* __restrict__ de_out)
{
    __shared__ union SM {
        ulonglong2 tt2[4][256];                                      // 16 KB
        struct { float4 part[16][17]; float evs[EDIM]; float hv[HDIM]; } node;
    } sm;
    __shared__ float psb_s[HDIM];

    const int sn  = blockIdx.x;           // s*256 + n  (n is also edge-row i)
    const int s   = sn >> 8;
    const int i   = sn & 255;
    const int tid = threadIdx.x;
    const int w   = tid >> 5;             // warp 0..7 == edge slot
    const int l   = tid & 31;             // lane
    const int c4  = l & 15;               // float4 slot in 64-wide channel dim
    const int r0  = w * 2 + (l >> 4);     // 0..15: row offset within 16-row groups
    const int c0  = l << 1;               // owned channels c0, c0+1

    const bool pf = ((c4 & 7) == 0) && (sn != NSN - 1);

    const float4* e0p = reinterpret_cast<const float4*>(e0)
                      + (size_t)sn * (KEDGE * EDIM / 4);

    // prologue (overlaps proj tail under PDL): buf rows 0..63 + prefetch 64..127
    float4 buf[4];
    #pragma unroll
    for (int u = 0; u < 4; u++) {
        const float4* p = &e0p[(u * 16 + r0) * 16 + c4];
        buf[u] = __ldcs(p);
        if (pf) asm volatile("prefetch.global.L2 [%0];" :: "l"(p + 1024));
    }

    // lane weights: h-pair packed for channels c0, c0+1 -> 16 ull (32 regs)
    ull wa[8], wb[8];
    #pragma unroll
    for (int m = 0; m < 8; m++) {
        wa[m] = pack2(we2[(2 * m) * VDIM + c0    ], we2[(2 * m + 1) * VDIM + c0    ]);
        wb[m] = pack2(we2[(2 * m) * VDIM + c0 + 1], we2[(2 * m + 1) * VDIM + c0 + 1]);
    }
    const ull Ba = pack2(be2[c0    ], 0.0f);   // bias folded into accum init
    const ull Bb = pack2(be2[c0 + 1], 0.0f);

    // ---- PDL gate: wait for proj_kernel grid completion (memory visible) ----
    cudaGridDependencySynchronize();

    if (tid < 4)
        reinterpret_cast<float4*>(psb_s)[tid] =
            reinterpret_cast<const float4*>(g_psb + sn * HDIM)[tid];
    __syncthreads();                      // psb_s visible

    // --- tanh table: thread k computes t[k][0..15] in natural order ---
    if (tid < KEDGE) {
        const int j = tid + (tid >= i);   // skip diagonal
        const float* prb = g_prT + s * HDIM * NNODE + j;
        #pragma unroll
        for (int m = 0; m < 4; m++) {
            float t0 = fast_tanh(__ldg(prb + (4 * m    ) * NNODE) + psb_s[4 * m    ]);
            float t1 = fast_tanh(__ldg(prb + (4 * m + 1) * NNODE) + psb_s[4 * m + 1]);
            float t2 = fast_tanh(__ldg(prb + (4 * m + 2) * NNODE) + psb_s[4 * m + 2]);
            float t3 = fast_tanh(__ldg(prb + (4 * m + 3) * NNODE) + psb_s[4 * m + 3]);
            sm.tt2[m][tid] = make_ulonglong2(pack2(t0, t1), pack2(t2, t3));
        }
    }
    __syncthreads();                      // table ready

    ull accA = 0, accB = 0;               // packed e0 partial sums
    float* outp = de_out + (size_t)sn * KEDGE * VDIM + c0;

#define EDGE_ITER(K) do {                                                      \
        const int k_ = (K);                                                    \
        if (k_ < KEDGE) {                                                      \
            ull Aa0 = Ba, Aa1 = 0, Ab0 = Bb, Ab1 = 0;                          \
            _Pragma("unroll")                                                  \
            for (int m = 0; m < 4; m++) {                                      \
                ulonglong2 tp = sm.tt2[m][k_];          /* broadcast LDS.128 */\
                asm("fma.rn.f32x2 %0, %1, %2, %0;" : "+l"(Aa0) : "l"(wa[2*m  ]), "l"(tp.x)); \
                asm("fma.rn.f32x2 %0, %1, %2, %0;" : "+l"(Ab0) : "l"(wb[2*m  ]), "l"(tp.x)); \
                asm("fma.rn.f32x2 %0, %1, %2, %0;" : "+l"(Aa1) : "l"(wa[2*m+1]), "l"(tp.y)); \
                asm("fma.rn.f32x2 %0, %1, %2, %0;" : "+l"(Ab1) : "l"(wb[2*m+1]), "l"(tp.y)); \
            }                                                                  \
            asm("add.rn.f32x2 %0, %0, %1;" : "+l"(Aa0) : "l"(Aa1));            \
            asm("add.rn.f32x2 %0, %0, %1;" : "+l"(Ab0) : "l"(Ab1));            \
            float a_lo, a_hi, b_lo, b_hi;                                      \
            asm("mov.b64 {%0, %1}, %2;" : "=f"(a_lo), "=f"(a_hi) : "l"(Aa0));  \
            asm("mov.b64 {%0, %1}, %2;" : "=f"(b_lo), "=f"(b_hi) : "l"(Ab0));  \
            float2 o_ = make_float2(a_lo + a_hi, b_lo + b_hi);                 \
            __stcs(reinterpret_cast<float2*>(outp + (size_t)k_ * VDIM), o_);   \
        }                                                                      \
    } while (0)

    // --- pipelined main loop: 16 groups; per group 2 edge iters + 1 LDG + 1 pf ---
    #pragma unroll 1
    for (int gb = 0; gb < 16; gb += 4) {
        #pragma unroll
        for (int u = 0; u < 4; u++) {
            const int g = gb + u;
            EDGE_ITER(16 * g     + w);
            EDGE_ITER(16 * g + 8 + w);
            // consume buf[u] (row group g), then refill with group g+4
            {
                float4 v = buf[u];
                const int r = g * 16 + r0;
                if (r < KEDGE) {
                    ull va = pack2(v.x, v.y), vb = pack2(v.z, v.w);
                    asm("add.rn.f32x2 %0, %0, %1;" : "+l"(accA) : "l"(va));
                    asm("add.rn.f32x2 %0, %0, %1;" : "+l"(accB) : "l"(vb));
                }
                const int rn = r + 64;
                const float4* p = &e0p[rn * 16 + c4];
                if (rn < KEDGE) buf[u] = __ldcs(p);
                // prefetch row rn+64 (may spill into next tile: still useful)
                if (pf) asm volatile("prefetch.global.L2 [%0];" :: "l"(p + 1024));
            }
        }
    }
#undef EDGE_ITER

    // --- node epilogue: reduce partials (reuse smem), tiny MLPs ---
    float4 acc;
    asm("mov.b64 {%0, %1}, %2;" : "=f"(acc.x), "=f"(acc.y) : "l"(accA));
    asm("mov.b64 {%0, %1}, %2;" : "=f"(acc.z), "=f"(acc.w) : "l"(accB));

    __syncthreads();                      // everyone done reading tt2
    sm.node.part[r0][c4] = acc;           // 16 owners x 16 c4 slots
    __syncthreads();

    if (tid < 16) {
        float4 p4 = sm.node.part[0][tid];
        #pragma unroll
        for (int g = 1; g < 16; g++) {
            float4 p = sm.node.part[g][tid];
            p4.x += p.x; p4.y += p.y; p4.z += p.z; p4.w += p.w;
        }
        reinterpret_cast<float4*>(sm.node.evs)[tid] = p4;
    }
    __syncthreads();

    if (tid < 16) {
        float v = bv1[tid];
        #pragma unroll
        for (int e = 0; e < EDIM; e++) v = fmaf(sm.node.evs[e], wv1[e * HDIM + tid], v);
        sm.node.hv[tid] = fast_tanh(v);
    }
    __syncthreads();

    if (tid < VDIM) {
        float v = bv2[tid];
        #pragma unroll
        for (int j = 0; j < HDIM; j++) v = fmaf(sm.node.hv[j], wv2[j * VDIM + tid], v);
        dv_out[(size_t)sn * VDIM + tid] = v;
    }
}

// ---------------------------------------------------------------------------
// inputs (metadata order): t, v0, e0, wv1, bv1, wv2, bv2, we1, be1, we2, be2,
//                          recv_idx, send_idx (idx arrays unused: analytic)
// output: dv (S,N,V) followed by de (S,N,N-1,E)
// ---------------------------------------------------------------------------
extern "C" void kernel_launch(void* const* d_in, const int* in_sizes, int n_in,
                              void* d_out, int out_size)
{
    const float* v0  = (const float*)d_in[1];
    const float* e0  = (const float*)d_in[2];
    const float* wv1 = (const float*)d_in[3];
    const float* bv1 = (const float*)d_in[4];
    const float* wv2 = (const float*)d_in[5];
    const float* bv2 = (const float*)d_in[6];
    const float* we1 = (const float*)d_in[7];
    const float* be1 = (const float*)d_in[8];
    const float* we2 = (const float*)d_in[9];
    const float* be2 = (const float*)d_in[10];

    float* dv_out = (float*)d_out;
    float* de_out = dv_out + (size_t)SDIM * NNODE * VDIM;

    proj_kernel<<<NSN / 16, 256>>>(v0, we1, be1);

    // PDL launch: mega may start while proj drains; the grid-dependency sync
    // inside mega gates the first g_prT/g_psb read on proj grid completion.
    cudaLaunchConfig_t cfg = {};
    cfg.gridDim  = dim3(NSN, 1, 1);
    cfg.blockDim = dim3(256, 1, 1);
    cfg.dynamicSmemBytes = 0;
    cudaLaunchAttribute attr[1];
    attr[0].id = cudaLaunchAttributeProgrammaticStreamSerialization;
    attr[0].val.programmaticStreamSerializationAllowed = 1;
    cfg.attrs = attr;
    cfg.numAttrs = 1;
    cudaLaunchKernelEx(&cfg, mega_kernel,
                       e0, wv1, bv1, wv2, bv2, we2, be2, dv_out, de_out);
}